// round 1
// baseline (speedup 1.0000x reference)
#include <cuda_runtime.h>
#include <math.h>

#define SEQ 512
#define BSZ 64
#define INP 512
#define HID 1024
#define NCTA 128          // 16 j-chunks x 8 k-chunks
#define SMEM2 (2 * 128 * 68 * 4)

// Per-step arrival counters for the software grid barrier.
__device__ unsigned g_cnt[SEQ];

__global__ void zero_cnt_kernel() {
    g_cnt[threadIdx.x] = 0u;
}

// ---------------------------------------------------------------------------
// Kernel 1: C[m][n] = sum_k A[m][k]*W[n][k] + b_ih[n] + b_hh[n]
// A = x_in flattened (32768 x 512), W = W_ih (1024 x 512), C = d_out (32768 x 1024)
// Tile 64x64x16, 128 threads, thread tile 8m x 4n.
// ---------------------------------------------------------------------------
__global__ __launch_bounds__(128) void gemm_xw_kernel(
    const float* __restrict__ A,
    const float* __restrict__ W,
    const float* __restrict__ b_ih,
    const float* __restrict__ b_hh,
    float* __restrict__ C)
{
    __shared__ float sA[16][68];   // [k][m]
    __shared__ float sB[16][68];   // [k][n]

    const int t  = threadIdx.x;
    const int n0 = blockIdx.x * 64;
    const int m0 = blockIdx.y * 64;
    const int tx = t & 15;     // n quad:  n = n0 + 4*tx + j
    const int ty = t >> 4;     // m oct:   m = m0 + 8*ty + i
    const int lr = t >> 1;     // load row (0..63)
    const int lk = (t & 1) * 8;

    float acc[8][4];
#pragma unroll
    for (int i = 0; i < 8; ++i)
#pragma unroll
        for (int j = 0; j < 4; ++j) acc[i][j] = 0.0f;

    const float* Arow = A + (size_t)(m0 + lr) * INP + lk;
    const float* Wrow = W + (size_t)(n0 + lr) * INP + lk;

    for (int k0 = 0; k0 < INP; k0 += 16) {
        float4 a0 = *(const float4*)(Arow + k0);
        float4 a1 = *(const float4*)(Arow + k0 + 4);
        float4 w0 = *(const float4*)(Wrow + k0);
        float4 w1 = *(const float4*)(Wrow + k0 + 4);
        __syncthreads();
        sA[lk + 0][lr] = a0.x; sA[lk + 1][lr] = a0.y;
        sA[lk + 2][lr] = a0.z; sA[lk + 3][lr] = a0.w;
        sA[lk + 4][lr] = a1.x; sA[lk + 5][lr] = a1.y;
        sA[lk + 6][lr] = a1.z; sA[lk + 7][lr] = a1.w;
        sB[lk + 0][lr] = w0.x; sB[lk + 1][lr] = w0.y;
        sB[lk + 2][lr] = w0.z; sB[lk + 3][lr] = w0.w;
        sB[lk + 4][lr] = w1.x; sB[lk + 5][lr] = w1.y;
        sB[lk + 6][lr] = w1.z; sB[lk + 7][lr] = w1.w;
        __syncthreads();
#pragma unroll
        for (int k = 0; k < 16; ++k) {
            float4 av0 = *(const float4*)&sA[k][ty * 8];
            float4 av1 = *(const float4*)&sA[k][ty * 8 + 4];
            float4 bv  = *(const float4*)&sB[k][tx * 4];
            float am[8] = {av0.x, av0.y, av0.z, av0.w, av1.x, av1.y, av1.z, av1.w};
            float bn[4] = {bv.x, bv.y, bv.z, bv.w};
#pragma unroll
            for (int i = 0; i < 8; ++i)
#pragma unroll
                for (int j = 0; j < 4; ++j)
                    acc[i][j] = fmaf(am[i], bn[j], acc[i][j]);
        }
    }

    float4 bi = *(const float4*)(b_ih + n0 + tx * 4);
    float4 bh = *(const float4*)(b_hh + n0 + tx * 4);
    float4 bias;
    bias.x = bi.x + bh.x; bias.y = bi.y + bh.y;
    bias.z = bi.z + bh.z; bias.w = bi.w + bh.w;

#pragma unroll
    for (int i = 0; i < 8; ++i) {
        float4 o;
        o.x = acc[i][0] + bias.x;
        o.y = acc[i][1] + bias.y;
        o.z = acc[i][2] + bias.z;
        o.w = acc[i][3] + bias.w;
        *(float4*)&C[(size_t)(m0 + ty * 8 + i) * HID + n0 + tx * 4] = o;
    }
}

// ---------------------------------------------------------------------------
// Kernel 2: persistent recurrence.
// CTA (jc,kc): owns W_hh[jc*64 .. +64) rows x [kc*128 .. +128) cols in smem.
// Per step s: read pre-acts of step s-1 (tanh on the fly), compute partial
// h[b] . W[j]^T over the k-chunk, atomicAdd into d_out[b][s][j], barrier.
// d_out holds PRE-activations until the final tanh pass.
// ---------------------------------------------------------------------------
__global__ __launch_bounds__(128) void rnn_step_kernel(
    const float* __restrict__ Whh,   // 1024 x 1024
    float* __restrict__ out)         // (64, 512, 1024) pre-seeded with xw+bias
{
    extern __shared__ float smem[];
    float* sW = smem;                // [128][68]: sW[k*68 + j_local]
    float* sh = smem + 128 * 68;     // [128][68]: sh[k*68 + b]

    const int t  = threadIdx.x;
    const int jc = blockIdx.x & 15;   // 0..15  (64 j each)
    const int kc = blockIdx.x >> 4;   // 0..7   (128 k each)

    // One-time W tile load (transposed to k-major).
    {
        const int j  = t >> 1;
        const int kh = (t & 1) * 64;
        const float* src = Whh + (size_t)(jc * 64 + j) * HID + kc * 128 + kh;
#pragma unroll
        for (int kk = 0; kk < 64; kk += 4) {
            float4 v = *(const float4*)(src + kk);
            sW[(kh + kk + 0) * 68 + j] = v.x;
            sW[(kh + kk + 1) * 68 + j] = v.y;
            sW[(kh + kk + 2) * 68 + j] = v.z;
            sW[(kh + kk + 3) * 68 + j] = v.w;
        }
    }
    __syncthreads();

    const int tb  = t & 15;          // b = 4*tb + i
    const int tj  = t >> 4;          // j_local = 8*tj + j
    const int tb4 = tb * 4;
    const int tj8 = tj * 8;
    const int bload  = t >> 1;       // 0..63
    const int khload = (t & 1) * 64; // 0 or 64

    for (int s = 1; s < SEQ; ++s) {
        if (s >= 2) {
            if (t == 0) {
                volatile unsigned* p = &g_cnt[s - 1];
                while (*p != (unsigned)NCTA) __nanosleep(32);
                __threadfence();
            }
            __syncthreads();
        }

        // Fill sh[k][b] = tanh(pre-act of step s-1). L1-bypass loads so we see
        // the L2-resident atomic results.
        {
            const float* src = out + ((size_t)(bload * SEQ + (s - 1))) * HID
                                   + kc * 128 + khload;
#pragma unroll
            for (int kk = 0; kk < 64; kk += 4) {
                float4 v = __ldcg((const float4*)(src + kk));
                sh[(khload + kk + 0) * 68 + bload] = tanhf(v.x);
                sh[(khload + kk + 1) * 68 + bload] = tanhf(v.y);
                sh[(khload + kk + 2) * 68 + bload] = tanhf(v.z);
                sh[(khload + kk + 3) * 68 + bload] = tanhf(v.w);
            }
        }
        __syncthreads();

        float acc[4][8];
#pragma unroll
        for (int i = 0; i < 4; ++i)
#pragma unroll
            for (int j = 0; j < 8; ++j) acc[i][j] = 0.0f;

#pragma unroll 4
        for (int k = 0; k < 128; ++k) {
            const float4 hv = *(const float4*)(sh + k * 68 + tb4);
            const float4 wa = *(const float4*)(sW + k * 68 + tj8);
            const float4 wb = *(const float4*)(sW + k * 68 + tj8 + 4);
            float hb[4] = {hv.x, hv.y, hv.z, hv.w};
            float wv[8] = {wa.x, wa.y, wa.z, wa.w, wb.x, wb.y, wb.z, wb.w};
#pragma unroll
            for (int i = 0; i < 4; ++i)
#pragma unroll
                for (int j = 0; j < 8; ++j)
                    acc[i][j] = fmaf(hb[i], wv[j], acc[i][j]);
        }

        // Accumulate partial results into the pre-act buffer for step s.
#pragma unroll
        for (int i = 0; i < 4; ++i) {
            const int b = tb4 + i;
            float* row = out + ((size_t)(b * SEQ + s)) * HID + jc * 64 + tj8;
#pragma unroll
            for (int j = 0; j < 8; ++j) atomicAdd(row + j, acc[i][j]);
        }

        __threadfence();
        __syncthreads();
        if (t == 0 && s < SEQ - 1) atomicAdd(&g_cnt[s], 1u);
    }
}

// ---------------------------------------------------------------------------
// Kernel 3: elementwise tanh over the whole output buffer.
// ---------------------------------------------------------------------------
__global__ __launch_bounds__(256) void tanh_kernel(float* __restrict__ out) {
    size_t i = ((size_t)blockIdx.x * blockDim.x + threadIdx.x) * 4;
    float4 v = *(float4*)(out + i);
    v.x = tanhf(v.x); v.y = tanhf(v.y);
    v.z = tanhf(v.z); v.w = tanhf(v.w);
    *(float4*)(out + i) = v;
}

extern "C" void kernel_launch(void* const* d_in, const int* in_sizes, int n_in,
                              void* d_out, int out_size) {
    const float* x   = (const float*)d_in[0];   // (64, 512, 512)
    const float* Wih = (const float*)d_in[1];   // (1024, 512)
    const float* Whh = (const float*)d_in[2];   // (1024, 1024)
    const float* bih = (const float*)d_in[3];   // (1024,)
    const float* bhh = (const float*)d_in[4];   // (1024,)
    float* out = (float*)d_out;                 // (64, 512, 1024)

    cudaFuncSetAttribute(rnn_step_kernel,
                         cudaFuncAttributeMaxDynamicSharedMemorySize, SMEM2);

    zero_cnt_kernel<<<1, SEQ>>>();

    dim3 g1(HID / 64, (BSZ * SEQ) / 64);
    gemm_xw_kernel<<<g1, 128>>>(x, Wih, bih, bhh, out);

    rnn_step_kernel<<<NCTA, 128, SMEM2>>>(Whh, out);

    tanh_kernel<<<(BSZ * SEQ * HID) / (256 * 4), 256>>>(out);
}